// round 7
// baseline (speedup 1.0000x reference)
#include <cuda_runtime.h>
#include <cuda_bf16.h>
#include <math.h>
#include <stdint.h>

#define BB 32
#define SS 512
#define HH 768
#define KK 4
#define HOPS 3
#define H2 1536
#define H3 2304
#define MROWS (BB*SS)

// ---------------- scratch (device globals; no allocation) ----------------
__device__ float g_WcT[(size_t)KK*HH*HH];          // Wc^T fp32 [k][b][i]
__device__ float g_bc[KK*HH];
__device__ float g_Whs[(size_t)KK*MROWS*HH];       // [K,B,S,H] 201MB
__device__ float g_Wht[KK*BB*HH];
__device__ float g_scores[KK*BB*SS];
__device__ float g_qbuf[BB*HH];
__device__ float g_hbuf[BB*HH];
__device__ float g_GX[BB*H3];
__device__ float g_GH[BB*H3];
__device__ int   g_idx[BB];
// bf16 splits for the small Wc GEMM
__device__ __nv_bfloat16 g_pwhi[(size_t)KK*HH*HH];
__device__ __nv_bfloat16 g_pwlo[(size_t)KK*HH*HH];
__device__ __nv_bfloat16 g_WsThi[(size_t)KK*HH*HH];
__device__ __nv_bfloat16 g_WsTlo[(size_t)KK*HH*HH];
// int8 quantized operands for the big GEMM
__device__ int8_t g_qAh[(size_t)MROWS*HH];
__device__ int8_t g_qAl[(size_t)MROWS*HH];
__device__ float  g_sa[MROWS];
__device__ int8_t g_qBh[(size_t)KK*HH*HH];
__device__ int8_t g_qBl[(size_t)KK*HH*HH];
__device__ float  g_sb[KK*HH];

// ---------------- helpers ----------------
__device__ __forceinline__ uint32_t smem_u32(const void* p) {
    uint32_t a;
    asm("{ .reg .u64 t; cvta.to.shared.u64 t, %1; cvt.u32.u64 %0, t; }" : "=r"(a) : "l"(p));
    return a;
}
__device__ __forceinline__ void mma16816(float* d, const uint32_t* a, const uint32_t* b) {
    asm volatile("mma.sync.aligned.m16n8k16.row.col.f32.bf16.bf16.f32 "
        "{%0,%1,%2,%3},{%4,%5,%6,%7},{%8,%9},{%0,%1,%2,%3};"
        : "+f"(d[0]), "+f"(d[1]), "+f"(d[2]), "+f"(d[3])
        : "r"(a[0]), "r"(a[1]), "r"(a[2]), "r"(a[3]), "r"(b[0]), "r"(b[1]));
}
__device__ __forceinline__ void mmaI(int* d, const uint32_t* a, const uint32_t* b) {
    asm volatile("mma.sync.aligned.m16n8k32.row.col.s32.s8.s8.s32 "
        "{%0,%1,%2,%3},{%4,%5,%6,%7},{%8,%9},{%0,%1,%2,%3};"
        : "+r"(d[0]), "+r"(d[1]), "+r"(d[2]), "+r"(d[3])
        : "r"(a[0]), "r"(a[1]), "r"(a[2]), "r"(a[3]), "r"(b[0]), "r"(b[1]));
}
__device__ __forceinline__ void ldsm4(uint32_t* r, uint32_t addr) {
    asm volatile("ldmatrix.sync.aligned.m8n8.x4.shared.b16 {%0,%1,%2,%3}, [%4];"
        : "=r"(r[0]), "=r"(r[1]), "=r"(r[2]), "=r"(r[3]) : "r"(addr));
}
__device__ __forceinline__ void cp16(uint32_t dst, const void* src) {
    asm volatile("cp.async.cg.shared.global [%0], [%1], 16;" :: "r"(dst), "l"(src));
}
#define CP_COMMIT() asm volatile("cp.async.commit_group;" ::: "memory")
#define CP_WAIT0()  asm volatile("cp.async.wait_group 0;" ::: "memory")

// ---------------- split helpers (for the small Wc GEMM) ----------------
__device__ __forceinline__ void split2(float x, __nv_bfloat16& h, __nv_bfloat16& l) {
    __nv_bfloat16 hb = __float2bfloat16(x);
    h = hb;
    l = __float2bfloat16(x - __bfloat162float(hb));
}

__global__ void k_split(const float* __restrict__ src, __nv_bfloat16* __restrict__ dhi,
                        __nv_bfloat16* __restrict__ dlo, int n) {
    int i = blockIdx.x * 256 + threadIdx.x;
    if (i < n) split2(src[i], dhi[i], dlo[i]);
}

// transpose + split: src [R=768, C=768] per batch -> dst [C, R]
__global__ void k_splitT(const float* __restrict__ src, __nv_bfloat16* __restrict__ dhi,
                         __nv_bfloat16* __restrict__ dlo) {
    __shared__ float t[32][33];
    int b = blockIdx.z;
    const float* S = src + (size_t)b * HH * HH;
    __nv_bfloat16* Dh = dhi + (size_t)b * HH * HH;
    __nv_bfloat16* Dl = dlo + (size_t)b * HH * HH;
    int r0 = blockIdx.y * 32, c0 = blockIdx.x * 32;
    for (int rr = threadIdx.y; rr < 32; rr += 8)
        t[rr][threadIdx.x] = S[(size_t)(r0 + rr) * HH + c0 + threadIdx.x];
    __syncthreads();
    for (int rr = threadIdx.y; rr < 32; rr += 8) {
        float v = t[threadIdx.x][rr];
        size_t o = (size_t)(c0 + rr) * HH + r0 + threadIdx.x;
        split2(v, Dh[o], Dl[o]);
    }
}

// ---------------- per-row int8 hi/lo quantizer ----------------
// x = s*(h + l/128), s = rowmax/127, |l|<=64. One block (256 thr) per row of 768.
__global__ void k_quant(const float* __restrict__ src, int8_t* __restrict__ h8,
                        int8_t* __restrict__ l8, float* __restrict__ sc) {
    __shared__ float red[8];
    int row = blockIdx.x, t = threadIdx.x;
    const float* p = src + (size_t)row * HH;
    float v0 = p[t], v1 = p[t + 256], v2 = p[t + 512];
    float m = fmaxf(fabsf(v0), fmaxf(fabsf(v1), fabsf(v2)));
    #pragma unroll
    for (int o = 16; o; o >>= 1) m = fmaxf(m, __shfl_xor_sync(0xffffffffu, m, o));
    if ((t & 31) == 0) red[t >> 5] = m;
    __syncthreads();
    if (t < 32) {
        float mm = (t < 8) ? red[t] : 0.f;
        #pragma unroll
        for (int o = 4; o; o >>= 1) mm = fmaxf(mm, __shfl_xor_sync(0xffffffffu, mm, o));
        if (t == 0) red[0] = mm;
    }
    __syncthreads();
    float mx = red[0];
    float s = mx * (1.f / 127.f);
    float inv = (mx > 0.f) ? (127.f / mx) : 0.f;
    if (t == 0) sc[row] = s;
    #pragma unroll
    for (int i = 0; i < 3; i++) {
        float x = (i == 0) ? v0 : (i == 1) ? v1 : v2;
        float q = x * inv;
        float hq = rintf(q);
        float l = rintf((q - hq) * 128.f);
        size_t o = (size_t)row * HH + t + i * 256;
        h8[o] = (int8_t)(int)hq;
        l8[o] = (int8_t)(int)l;
    }
}

// ---------------- HMMA split-bf16 GEMM (small Wc GEMM only) ----------------
#define ROWP 40
#define ROWB (ROWP*2)                  // 80 bytes
#define ARRB (128*ROWB)
#define STG3 (4*ARRB)
#define SMEM3 (2*STG3)

__global__ __launch_bounds__(256, 2)
void k_hmma3(const __nv_bfloat16* __restrict__ Ahi, const __nv_bfloat16* __restrict__ Alo,
             size_t strideA,
             const __nv_bfloat16* __restrict__ Bhi, const __nv_bfloat16* __restrict__ Blo,
             size_t strideB,
             float* __restrict__ C, size_t strideC,
             const float* __restrict__ bias, int Kd)
{
    extern __shared__ char smem[];
    const uint32_t sb = smem_u32(smem);
    const int tid = threadIdx.x;
    const int lane = tid & 31;
    const int warp = tid >> 5;
    const int wm = warp >> 2, wn = warp & 3;
    const int bat = blockIdx.z;
    const int m0 = blockIdx.y * 128;
    const int n0 = blockIdx.x * 128;

    const int r0 = tid >> 2, cj = tid & 3;
    const __nv_bfloat16* bAh = Ahi + (size_t)bat * strideA + (size_t)(m0 + r0) * Kd + cj * 8;
    const __nv_bfloat16* bAl = Alo + (size_t)bat * strideA + (size_t)(m0 + r0) * Kd + cj * 8;
    const __nv_bfloat16* bBh = Bhi + (size_t)bat * strideB + (size_t)(n0 + r0) * Kd + cj * 8;
    const __nv_bfloat16* bBl = Blo + (size_t)bat * strideB + (size_t)(n0 + r0) * Kd + cj * 8;
    const size_t rstep = (size_t)64 * Kd;
    const uint32_t d0 = (uint32_t)r0 * ROWB + (uint32_t)cj * 16;
    const uint32_t d1 = d0 + 64 * ROWB;

    float acc[4][4][4];
    #pragma unroll
    for (int mi = 0; mi < 4; mi++)
        #pragma unroll
        for (int ni = 0; ni < 4; ni++)
            #pragma unroll
            for (int j = 0; j < 4; j++) acc[mi][ni][j] = 0.f;

    const int nIt = Kd / 32;

#define LOAD3(it) do {                                            \
        uint32_t s_ = sb + ((it) & 1) * STG3;                     \
        int ko_ = (it) * 32;                                      \
        cp16(s_ + 0*ARRB + d0, bAh + ko_);                        \
        cp16(s_ + 0*ARRB + d1, bAh + rstep + ko_);                \
        cp16(s_ + 1*ARRB + d0, bAl + ko_);                        \
        cp16(s_ + 1*ARRB + d1, bAl + rstep + ko_);                \
        cp16(s_ + 2*ARRB + d0, bBh + ko_);                        \
        cp16(s_ + 2*ARRB + d1, bBh + rstep + ko_);                \
        cp16(s_ + 3*ARRB + d0, bBl + ko_);                        \
        cp16(s_ + 3*ARRB + d1, bBl + rstep + ko_);                \
        CP_COMMIT();                                              \
    } while (0)

    LOAD3(0);

    const int grp = lane >> 3, lr = lane & 7;
    const uint32_t aoff = (uint32_t)(wm * 64 + (grp & 1) * 8 + lr) * ROWB + (uint32_t)(grp >> 1) * 16;
    const uint32_t boff = (uint32_t)(wn * 32 + (grp >> 1) * 8 + lr) * ROWB + (uint32_t)(grp & 1) * 16;

    for (int it = 0; it < nIt; ++it) {
        CP_WAIT0();
        __syncthreads();
        if (it + 1 < nIt) LOAD3(it + 1);

        const uint32_t st = sb + (it & 1) * STG3;
        const uint32_t pAh = st + 0*ARRB + aoff;
        const uint32_t pAl = st + 1*ARRB + aoff;
        const uint32_t pBh = st + 2*ARRB + boff;
        const uint32_t pBl = st + 3*ARRB + boff;

        #pragma unroll
        for (int ks = 0; ks < 2; ks++) {
            const uint32_t kb2 = ks * 32;
            uint32_t ah[4][4], al[4][4];
            #pragma unroll
            for (int mi = 0; mi < 4; mi++) {
                ldsm4(ah[mi], pAh + (uint32_t)mi * (16 * ROWB) + kb2);
                ldsm4(al[mi], pAl + (uint32_t)mi * (16 * ROWB) + kb2);
            }
            #pragma unroll
            for (int pg = 0; pg < 2; pg++) {
                uint32_t bh[4], bl[4];
                ldsm4(bh, pBh + (uint32_t)pg * (16 * ROWB) + kb2);
                ldsm4(bl, pBl + (uint32_t)pg * (16 * ROWB) + kb2);
                #pragma unroll
                for (int mi = 0; mi < 4; mi++) {
                    mma16816(acc[mi][2*pg],   ah[mi], bh);
                    mma16816(acc[mi][2*pg+1], ah[mi], bh + 2);
                }
                #pragma unroll
                for (int mi = 0; mi < 4; mi++) {
                    mma16816(acc[mi][2*pg],   ah[mi], bl);
                    mma16816(acc[mi][2*pg+1], ah[mi], bl + 2);
                }
                #pragma unroll
                for (int mi = 0; mi < 4; mi++) {
                    mma16816(acc[mi][2*pg],   al[mi], bh);
                    mma16816(acc[mi][2*pg+1], al[mi], bh + 2);
                }
            }
        }
    }
#undef LOAD3

    const int r = lane >> 2, c2 = (lane & 3) * 2;
    const float* bb = bias ? (bias + (size_t)bat * HH) : nullptr;
    float* Cb = C + (size_t)bat * strideC;
    #pragma unroll
    for (int ni = 0; ni < 4; ni++) {
        int col = n0 + wn * 32 + ni * 8 + c2;
        float bx = bb ? bb[col] : 0.f;
        float by = bb ? bb[col + 1] : 0.f;
        #pragma unroll
        for (int mi = 0; mi < 4; mi++) {
            int row = m0 + wm * 64 + mi * 16 + r;
            float2 v0 = make_float2(acc[mi][ni][0] + bx, acc[mi][ni][1] + by);
            float2 v1 = make_float2(acc[mi][ni][2] + bx, acc[mi][ni][3] + by);
            *(float2*)(Cb + (size_t)row * HH + col) = v0;
            *(float2*)(Cb + (size_t)(row + 8) * HH + col) = v1;
        }
    }
}

// ---------------- IMMA int8 hi/lo GEMM (big W_hs GEMM) ----------------
// C[m,n] = sa[m]*sb[n]*(P_hh + P_mix/128) + bias[n]
// BM=128, BN=64, BK=64 bytes; 8 warps (2x4), warp tile 64x16; 2-stage; occ 2.
#define QROWB 80
#define QA_H 0
#define QA_L (128*QROWB)
#define QB_H (2*128*QROWB)
#define QB_L (QB_H + 64*QROWB)
#define QSTG (QB_L + 64*QROWB)         // 30720
#define QSMEM (2*QSTG)                  // 61440

__global__ __launch_bounds__(256, 2)
void k_imma(const int8_t* __restrict__ Ah8, const int8_t* __restrict__ Al8,
            const float* __restrict__ sa,
            const int8_t* __restrict__ Bh8, const int8_t* __restrict__ Bl8,
            const float* __restrict__ sbv,
            float* __restrict__ C, const float* __restrict__ bias)
{
    extern __shared__ char smem[];
    const uint32_t sbm = smem_u32(smem);
    const int tid = threadIdx.x;
    const int lane = tid & 31;
    const int warp = tid >> 5;
    const int wm = warp >> 2, wn = warp & 3;      // warp tile 64x16
    const int bat = blockIdx.z;
    const int m0 = blockIdx.y * 128;
    const int n0 = blockIdx.x * 64;

    // cp.async: 1536 16B chunks/stage = 6 per thread
    const int8_t* gsrc[6];
    uint32_t dsto[6];
    {
        const int8_t* bAh = Ah8 + (size_t)m0 * HH;
        const int8_t* bAl = Al8 + (size_t)m0 * HH;
        const int8_t* bBh = Bh8 + (size_t)bat * HH * HH + (size_t)n0 * HH;
        const int8_t* bBl = Bl8 + (size_t)bat * HH * HH + (size_t)n0 * HH;
        #pragma unroll
        for (int i = 0; i < 6; i++) {
            int id = i * 256 + tid;
            int cj = id & 3, rid = id >> 2;
            const int8_t* bp; uint32_t ao; int row;
            if (rid < 128)      { bp = bAh; ao = QA_H; row = rid; }
            else if (rid < 256) { bp = bAl; ao = QA_L; row = rid - 128; }
            else if (rid < 320) { bp = bBh; ao = QB_H; row = rid - 256; }
            else                { bp = bBl; ao = QB_L; row = rid - 320; }
            gsrc[i] = bp + (size_t)row * HH + cj * 16;
            dsto[i] = ao + (uint32_t)row * QROWB + (uint32_t)cj * 16;
        }
    }

    int accH[4][2][4], accM[4][2][4];
    #pragma unroll
    for (int mi = 0; mi < 4; mi++)
        #pragma unroll
        for (int nt = 0; nt < 2; nt++)
            #pragma unroll
            for (int j = 0; j < 4; j++) { accH[mi][nt][j] = 0; accM[mi][nt][j] = 0; }

    const int nIt = HH / 64;

#define QLOAD(it) do {                                        \
        uint32_t s_ = sbm + ((it) & 1) * QSTG;                \
        int ko_ = (it) * 64;                                  \
        _Pragma("unroll")                                     \
        for (int i_ = 0; i_ < 6; i_++)                        \
            cp16(s_ + dsto[i_], gsrc[i_] + ko_);              \
        CP_COMMIT();                                          \
    } while (0)

    QLOAD(0);

    const int grp = lane >> 3, lr = lane & 7;
    const uint32_t aoff = (uint32_t)(wm * 64 + (grp & 1) * 8 + lr) * QROWB + (uint32_t)(grp >> 1) * 16;
    const uint32_t boff = (uint32_t)(wn * 16 + (grp >> 1) * 8 + lr) * QROWB + (uint32_t)(grp & 1) * 16;

    for (int it = 0; it < nIt; ++it) {
        CP_WAIT0();
        __syncthreads();
        if (it + 1 < nIt) QLOAD(it + 1);

        const uint32_t st = sbm + (it & 1) * QSTG;
        const uint32_t pAh = st + QA_H + aoff;
        const uint32_t pAl = st + QA_L + aoff;
        const uint32_t pBh = st + QB_H + boff;
        const uint32_t pBl = st + QB_L + boff;

        #pragma unroll
        for (int ks = 0; ks < 2; ks++) {
            const uint32_t kb = ks * 32;                    // 32 bytes = k32
            uint32_t bh[4], bl[4];
            ldsm4(bh, pBh + kb);                            // 2 n8-tiles x k32
            ldsm4(bl, pBl + kb);
            #pragma unroll
            for (int mi = 0; mi < 4; mi++) {
                uint32_t ah[4], al[4];
                ldsm4(ah, pAh + (uint32_t)mi * (16 * QROWB) + kb);
                ldsm4(al, pAl + (uint32_t)mi * (16 * QROWB) + kb);
                #pragma unroll
                for (int nt = 0; nt < 2; nt++) {
                    mmaI(accH[mi][nt], ah, bh + 2*nt);
                    mmaI(accM[mi][nt], ah, bl + 2*nt);
                    mmaI(accM[mi][nt], al, bh + 2*nt);
                }
            }
        }
    }
#undef QLOAD

    // epilogue
    const int r = lane >> 2, c2 = (lane & 3) * 2;
    const float* bb = bias + (size_t)bat * HH;
    const float* sbp = sbv + (size_t)bat * HH;
    float* Cb = C + (size_t)bat * MROWS * HH;
    #pragma unroll
    for (int nt = 0; nt < 2; nt++) {
        int col = n0 + wn * 16 + nt * 8 + c2;
        float s0 = sbp[col], s1 = sbp[col + 1];
        float bx = bb[col], by = bb[col + 1];
        #pragma unroll
        for (int mi = 0; mi < 4; mi++) {
            int row = m0 + wm * 64 + mi * 16 + r;
            float sa0 = sa[row], sa8 = sa[row + 8];
            float2 v0, v1;
            v0.x = sa0 * s0 * ((float)accH[mi][nt][0] + (float)accM[mi][nt][0] * 0.0078125f) + bx;
            v0.y = sa0 * s1 * ((float)accH[mi][nt][1] + (float)accM[mi][nt][1] * 0.0078125f) + by;
            v1.x = sa8 * s0 * ((float)accH[mi][nt][2] + (float)accM[mi][nt][2] * 0.0078125f) + bx;
            v1.y = sa8 * s1 * ((float)accH[mi][nt][3] + (float)accM[mi][nt][3] * 0.0078125f) + by;
            *(float2*)(Cb + (size_t)row * HH + col) = v0;
            *(float2*)(Cb + (size_t)(row + 8) * HH + col) = v1;
        }
    }
}

// ---------------- prologue: qbuf = question, h = 0 ----------------
__global__ void k_prologue(const float* __restrict__ question) {
    int t = blockIdx.x * 256 + threadIdx.x;
    if (t < BB*HH) { g_qbuf[t] = question[t]; g_hbuf[t] = 0.f; }
}

// ---------------- combined bias: bc[k][j] = pw_b[k] @ Ws_W[k] + Ws_b[k] ----------------
__global__ void k_bc(const float* __restrict__ pw_b, const float* __restrict__ Ws_W,
                     const float* __restrict__ Ws_b) {
    int k = blockIdx.x;
    int j = blockIdx.y * 256 + threadIdx.x;
    float acc = Ws_b[k*HH + j];
    const float* W = Ws_W + (size_t)k*HH*HH;
    const float* b = pw_b + k*HH;
    #pragma unroll 4
    for (int m = 0; m < HH; m++) acc = fmaf(b[m], W[(size_t)m*HH + j], acc);
    g_bc[k*HH + j] = acc;
}

// ---------------- W_ht = qbuf @ Wt_W[k] + Wt_b[k]  (k-split, atomic) ----------------
__global__ void k_init_wht(const float* __restrict__ Wt_b) {
    int t = blockIdx.x * 256 + threadIdx.x;
    if (t < KK*BB*HH) {
        int k = t / (BB*HH);
        int j = t % HH;
        g_Wht[t] = Wt_b[k*HH + j];
    }
}

__global__ void k_wht(const float* __restrict__ Wt_W) {
    int k  = blockIdx.x;
    int jc = blockIdx.y;
    int hs = blockIdx.z;
    int t  = threadIdx.x;
    int j  = jc*128 + t;
    int h0 = hs*128;
    __shared__ float qs[32][128];
    #pragma unroll 8
    for (int r = 0; r < 32; r++) qs[r][t] = g_qbuf[r*HH + h0 + t];
    __syncthreads();
    float acc[32];
    #pragma unroll
    for (int b = 0; b < 32; b++) acc[b] = 0.f;
    for (int hh = 0; hh < 128; hh++) {
        float w = Wt_W[((size_t)k*HH + h0 + hh)*HH + j];
        #pragma unroll
        for (int b = 0; b < 32; b++) acc[b] = fmaf(qs[b][hh], w, acc[b]);
    }
    #pragma unroll
    for (int b = 0; b < 32; b++) atomicAdd(&g_Wht[(k*BB + b)*HH + j], acc[b]);
}

// ---------------- scores[k,b,s] = We . tanh(W_hs + W_ht) + We_b ----------------
__global__ __launch_bounds__(256)
void k_scores(const float* __restrict__ WeW, const float* __restrict__ Web) {
    int kb = blockIdx.x;
    int sc = blockIdx.y;
    int k = kb / BB;
    __shared__ float4 shW[HH/4];
    __shared__ float4 shE[HH/4];
    if (threadIdx.x < HH/4) {
        shW[threadIdx.x] = ((const float4*)(g_Wht + (size_t)kb*HH))[threadIdx.x];
        shE[threadIdx.x] = ((const float4*)(WeW + (size_t)k*HH))[threadIdx.x];
    }
    __syncthreads();
    int warp = threadIdx.x >> 5, lane = threadIdx.x & 31;
    float web = Web[k];
    for (int s = sc*128 + warp; s < sc*128 + 128; s += 8) {
        const float4* row = (const float4*)(g_Whs + ((size_t)kb*SS + s)*HH);
        float sum = 0.f;
        #pragma unroll
        for (int i = 0; i < 6; i++) {
            int idx = lane + i*32;
            float4 v = row[idx];
            float4 w = shW[idx];
            float4 e = shE[idx];
            float x0 = v.x + w.x, x1 = v.y + w.y, x2 = v.z + w.z, x3 = v.w + w.w;
            float t0 = 1.f - __fdividef(2.f, __expf(2.f*x0) + 1.f);
            float t1 = 1.f - __fdividef(2.f, __expf(2.f*x1) + 1.f);
            float t2 = 1.f - __fdividef(2.f, __expf(2.f*x2) + 1.f);
            float t3 = 1.f - __fdividef(2.f, __expf(2.f*x3) + 1.f);
            sum = fmaf(t0, e.x, sum);
            sum = fmaf(t1, e.y, sum);
            sum = fmaf(t2, e.z, sum);
            sum = fmaf(t3, e.w, sum);
        }
        #pragma unroll
        for (int o = 16; o; o >>= 1) sum += __shfl_xor_sync(0xffffffffu, sum, o);
        if (lane == 0) g_scores[kb*SS + s] = sum + web;
    }
}

// ---------------- softmax over S, in place ----------------
__global__ void k_softmax() {
    __shared__ float red[256];
    int row = blockIdx.x;
    float* p = g_scores + (size_t)row * SS;
    int t = threadIdx.x;
    float a = p[t], b = p[t + 256];
    red[t] = fmaxf(a, b);
    __syncthreads();
    for (int o = 128; o; o >>= 1) { if (t < o) red[t] = fmaxf(red[t], red[t+o]); __syncthreads(); }
    float m = red[0];
    __syncthreads();
    float e0 = __expf(a - m), e1 = __expf(b - m);
    red[t] = e0 + e1;
    __syncthreads();
    for (int o = 128; o; o >>= 1) { if (t < o) red[t] += red[t+o]; __syncthreads(); }
    float inv = 1.f / red[0];
    p[t] = e0 * inv;
    p[t + 256] = e1 * inv;
}

// ---------------- alpha_linear, prob (hop 0), argmax ----------------
__global__ void k_alpha(const float* __restrict__ hw, const float* __restrict__ hb,
                        float* __restrict__ out_prob, int hop) {
    int b = blockIdx.x;
    int s = threadIdx.x;
    float al = hb[0];
    #pragma unroll
    for (int k = 0; k < KK; k++) al = fmaf(g_scores[(k*BB + b)*SS + s], hw[k], al);
    __shared__ float ssq[512];
    __shared__ float sval[512];
    __shared__ int   sidx[512];
    ssq[s] = al * al; sval[s] = al; sidx[s] = s;
    __syncthreads();
    for (int o = 256; o; o >>= 1) {
        if (s < o) {
            ssq[s] += ssq[s + o];
            float v2 = sval[s + o]; int i2 = sidx[s + o];
            if (v2 > sval[s] || (v2 == sval[s] && i2 < sidx[s])) { sval[s] = v2; sidx[s] = i2; }
        }
        __syncthreads();
    }
    if (s == 0) g_idx[b] = sidx[0];
    if (hop == 0) out_prob[b*SS + s] = al / sqrtf(ssq[0]);
}

// ---------------- GRU ----------------
__global__ void k_gru_init(const float* __restrict__ bih, const float* __restrict__ bhh) {
    int t = blockIdx.x * 256 + threadIdx.x;
    if (t < BB*H3) { int j = t % H3; g_GX[t] = bih[j]; g_GH[t] = bhh[j]; }
}

__global__ void k_grugemm(const float* __restrict__ Wih, const float* __restrict__ Whh,
                          const float* __restrict__ text) {
    int jc = blockIdx.x;
    int ks = blockIdx.y;
    int bg = blockIdx.z;
    int t = threadIdx.x;
    int j = jc*256 + t;
    int i0 = ks*256;
    __shared__ float xs[8][256];
    int i = i0 + t;
    #pragma unroll
    for (int r = 0; r < 8; r++) {
        int b = bg*8 + r;
        float v;
        if (i < 768)       v = g_qbuf[b*HH + i];
        else if (i < 1536) v = text[((size_t)b*SS + g_idx[b])*HH + (i - 768)];
        else               v = g_hbuf[b*HH + (i - 1536)];
        xs[r][t] = v;
    }
    __syncthreads();
    const float* W; int wi0; float* G;
    if (i0 < 1536) { W = Wih; wi0 = i0;        G = g_GX; }
    else           { W = Whh; wi0 = i0 - 1536; G = g_GH; }
    float acc[8];
    #pragma unroll
    for (int r = 0; r < 8; r++) acc[r] = 0.f;
    #pragma unroll 4
    for (int kk = 0; kk < 256; kk++) {
        float w = W[(size_t)(wi0 + kk)*H3 + j];
        #pragma unroll
        for (int r = 0; r < 8; r++) acc[r] = fmaf(xs[r][kk], w, acc[r]);
    }
    #pragma unroll
    for (int r = 0; r < 8; r++) atomicAdd(&G[(bg*8 + r)*H3 + j], acc[r]);
}

__global__ void k_grugate(float* __restrict__ out_h, int hop) {
    int t = blockIdx.x * 256 + threadIdx.x;
    if (t >= BB*HH) return;
    int b = t / HH, j = t % HH;
    float gxr = g_GX[b*H3 + j],        ghr = g_GH[b*H3 + j];
    float gxz = g_GX[b*H3 + HH + j],   ghz = g_GH[b*H3 + HH + j];
    float gxn = g_GX[b*H3 + 2*HH + j], ghn = g_GH[b*H3 + 2*HH + j];
    float r = 1.f / (1.f + expf(-(gxr + ghr)));
    float z = 1.f / (1.f + expf(-(gxz + ghz)));
    float n = tanhf(gxn + r * ghn);
    float hprev = g_hbuf[t];
    float hn = (1.f - z) * n + z * hprev;
    g_hbuf[t] = hn;
    g_qbuf[t] = hn;
    out_h[((size_t)b*HOPS + hop)*HH + j] = hn;
}

// ---------------- launch ----------------
extern "C" void kernel_launch(void* const* d_in, const int* in_sizes, int n_in,
                              void* d_out, int out_size) {
    const float* question = (const float*)d_in[0];
    const float* text     = (const float*)d_in[1];
    const float* pw_W     = (const float*)d_in[2];
    const float* pw_b     = (const float*)d_in[3];
    const float* Ws_W     = (const float*)d_in[4];
    const float* Ws_b     = (const float*)d_in[5];
    const float* Wt_W     = (const float*)d_in[6];
    const float* Wt_b     = (const float*)d_in[7];
    const float* We_W     = (const float*)d_in[8];
    const float* We_b     = (const float*)d_in[9];
    const float* headw_W  = (const float*)d_in[10];
    const float* headw_b  = (const float*)d_in[11];
    const float* gru_Wih  = (const float*)d_in[12];
    const float* gru_Whh  = (const float*)d_in[13];
    const float* gru_bih  = (const float*)d_in[14];
    const float* gru_bhh  = (const float*)d_in[15];

    float* out_prob = (float*)d_out;
    float* out_h    = (float*)d_out + BB*SS;

    float *p_WcT, *p_bc, *p_Whs, *p_sa, *p_sb;
    __nv_bfloat16 *p_pwhi, *p_pwlo, *p_WsThi, *p_WsTlo;
    int8_t *p_qAh, *p_qAl, *p_qBh, *p_qBl;
    cudaGetSymbolAddress((void**)&p_WcT,   g_WcT);
    cudaGetSymbolAddress((void**)&p_bc,    g_bc);
    cudaGetSymbolAddress((void**)&p_Whs,   g_Whs);
    cudaGetSymbolAddress((void**)&p_pwhi,  g_pwhi);
    cudaGetSymbolAddress((void**)&p_pwlo,  g_pwlo);
    cudaGetSymbolAddress((void**)&p_WsThi, g_WsThi);
    cudaGetSymbolAddress((void**)&p_WsTlo, g_WsTlo);
    cudaGetSymbolAddress((void**)&p_qAh,   g_qAh);
    cudaGetSymbolAddress((void**)&p_qAl,   g_qAl);
    cudaGetSymbolAddress((void**)&p_qBh,   g_qBh);
    cudaGetSymbolAddress((void**)&p_qBl,   g_qBl);
    cudaGetSymbolAddress((void**)&p_sa,    g_sa);
    cudaGetSymbolAddress((void**)&p_sb,    g_sb);

    cudaFuncSetAttribute(k_hmma3, cudaFuncAttributeMaxDynamicSharedMemorySize, SMEM3);
    cudaFuncSetAttribute(k_imma,  cudaFuncAttributeMaxDynamicSharedMemorySize, QSMEM);

    k_prologue<<<(BB*HH + 255)/256, 256>>>(question);
    k_bc<<<dim3(KK, HH/256), 256>>>(pw_b, Ws_W, Ws_b);

    // quantize text rows (A operand)
    k_quant<<<MROWS, 256>>>(text, p_qAh, p_qAl, p_sa);

    // bf16 splits for the small Wc GEMM
    k_split<<<(KK*HH*HH + 255)/256, 256>>>(pw_W, p_pwhi, p_pwlo, KK*HH*HH);
    k_splitT<<<dim3(HH/32, HH/32, KK), dim3(32, 8)>>>(Ws_W, p_WsThi, p_WsTlo);

    // WcT[k] = WsT[k] (.) pw[k]  ->  WcT[b][i] row-major (operand swap)
    k_hmma3<<<dim3(HH/128, HH/128, KK), 256, SMEM3>>>(
        p_WsThi, p_WsTlo, (size_t)HH*HH,
        p_pwhi, p_pwlo, (size_t)HH*HH,
        p_WcT, (size_t)HH*HH, nullptr, HH);

    // quantize WcT rows (B operand)
    k_quant<<<KK*HH, 256>>>(p_WcT, p_qBh, p_qBl, p_sb);

    // W_hs[k] = text @ Wc[k] + bc[k]  (IMMA int8 hi/lo)
    k_imma<<<dim3(HH/64, MROWS/128, KK), 256, QSMEM>>>(
        p_qAh, p_qAl, p_sa, p_qBh, p_qBl, p_sb, p_Whs, p_bc);

    for (int hop = 0; hop < HOPS; hop++) {
        k_init_wht<<<(KK*BB*HH + 255)/256, 256>>>(Wt_b);
        k_wht<<<dim3(KK, HH/128, HH/128), 128>>>(Wt_W);
        k_scores<<<dim3(KK*BB, SS/128), 256>>>(We_W, We_b);
        k_softmax<<<KK*BB, 256>>>();
        k_alpha<<<BB, 512>>>(headw_W, headw_b, out_prob, hop);
        k_gru_init<<<(BB*H3 + 255)/256, 256>>>(gru_bih, gru_bhh);
        k_grugemm<<<dim3(H3/256, H3/256, BB/8), 256>>>(gru_Wih, gru_Whh, text);
        k_grugate<<<(BB*HH + 255)/256, 256>>>(out_h, hop);
    }
}

// round 8
// speedup vs baseline: 2.1500x; 2.1500x over previous
#include <cuda_runtime.h>
#include <cuda_bf16.h>
#include <cuda_fp16.h>
#include <math.h>
#include <stdint.h>

#define BB 32
#define SS 512
#define HH 768
#define KK 4
#define HOPS 3
#define H2 1536
#define H3 2304
#define MROWS (BB*SS)

// ---------------- scratch (device globals; no allocation) ----------------
__device__ float g_WcT[(size_t)KK*HH*HH];          // Wc^T fp32 [k][j][i]
__device__ float g_bc[KK*HH];
__device__ __half g_Whs[(size_t)KK*MROWS*HH];      // [K,B,S,H] fp16 100MB
__device__ float g_Wht[KK*BB*HH];
__device__ float g_scores[KK*BB*SS];
__device__ float g_qbuf[BB*HH];
__device__ float g_hbuf[BB*HH];
__device__ float g_GX[BB*H3];
__device__ float g_GH[BB*H3];
__device__ int   g_idx[BB];
// bf16 splits for the small Wc GEMM
__device__ __nv_bfloat16 g_pwhi[(size_t)KK*HH*HH];
__device__ __nv_bfloat16 g_pwlo[(size_t)KK*HH*HH];
__device__ __nv_bfloat16 g_WsThi[(size_t)KK*HH*HH];
__device__ __nv_bfloat16 g_WsTlo[(size_t)KK*HH*HH];
// fp16 operands for the big GEMM
__device__ __half g_tAh[(size_t)MROWS*HH];
__device__ __half g_tAl[(size_t)MROWS*HH];
__device__ __half g_Bh[(size_t)KK*HH*HH];

// ---------------- helpers ----------------
__device__ __forceinline__ uint32_t smem_u32(const void* p) {
    uint32_t a;
    asm("{ .reg .u64 t; cvta.to.shared.u64 t, %1; cvt.u32.u64 %0, t; }" : "=r"(a) : "l"(p));
    return a;
}
__device__ __forceinline__ void mma16816(float* d, const uint32_t* a, const uint32_t* b) {
    asm volatile("mma.sync.aligned.m16n8k16.row.col.f32.bf16.bf16.f32 "
        "{%0,%1,%2,%3},{%4,%5,%6,%7},{%8,%9},{%0,%1,%2,%3};"
        : "+f"(d[0]), "+f"(d[1]), "+f"(d[2]), "+f"(d[3])
        : "r"(a[0]), "r"(a[1]), "r"(a[2]), "r"(a[3]), "r"(b[0]), "r"(b[1]));
}
__device__ __forceinline__ void mmaF16(float* d, const uint32_t* a, const uint32_t* b) {
    asm volatile("mma.sync.aligned.m16n8k16.row.col.f32.f16.f16.f32 "
        "{%0,%1,%2,%3},{%4,%5,%6,%7},{%8,%9},{%0,%1,%2,%3};"
        : "+f"(d[0]), "+f"(d[1]), "+f"(d[2]), "+f"(d[3])
        : "r"(a[0]), "r"(a[1]), "r"(a[2]), "r"(a[3]), "r"(b[0]), "r"(b[1]));
}
__device__ __forceinline__ void ldsm4(uint32_t* r, uint32_t addr) {
    asm volatile("ldmatrix.sync.aligned.m8n8.x4.shared.b16 {%0,%1,%2,%3}, [%4];"
        : "=r"(r[0]), "=r"(r[1]), "=r"(r[2]), "=r"(r[3]) : "r"(addr));
}
__device__ __forceinline__ void cp16(uint32_t dst, const void* src) {
    asm volatile("cp.async.cg.shared.global [%0], [%1], 16;" :: "r"(dst), "l"(src));
}
#define CP_COMMIT() asm volatile("cp.async.commit_group;" ::: "memory")
#define CP_WAIT0()  asm volatile("cp.async.wait_group 0;" ::: "memory")

// ---------------- split helpers ----------------
__device__ __forceinline__ void split2(float x, __nv_bfloat16& h, __nv_bfloat16& l) {
    __nv_bfloat16 hb = __float2bfloat16(x);
    h = hb;
    l = __float2bfloat16(x - __bfloat162float(hb));
}

__global__ void k_split(const float* __restrict__ src, __nv_bfloat16* __restrict__ dhi,
                        __nv_bfloat16* __restrict__ dlo, int n) {
    int i = blockIdx.x * 256 + threadIdx.x;
    if (i < n) split2(src[i], dhi[i], dlo[i]);
}

// fp16 hi/lo split (22-bit representation)
__global__ void k_splitH(const float* __restrict__ src, __half* __restrict__ dhi,
                         __half* __restrict__ dlo, int n) {
    int i = blockIdx.x * 256 + threadIdx.x;
    if (i < n) {
        float x = src[i];
        __half h = __float2half_rn(x);
        dhi[i] = h;
        dlo[i] = __float2half_rn(x - __half2float(h));
    }
}

// fp32 -> fp16 single
__global__ void k_cvtH(const float* __restrict__ src, __half* __restrict__ dst, int n) {
    int i = blockIdx.x * 256 + threadIdx.x;
    if (i < n) dst[i] = __float2half_rn(src[i]);
}

// transpose + split: src [R=768, C=768] per batch -> dst [C, R]
__global__ void k_splitT(const float* __restrict__ src, __nv_bfloat16* __restrict__ dhi,
                         __nv_bfloat16* __restrict__ dlo) {
    __shared__ float t[32][33];
    int b = blockIdx.z;
    const float* S = src + (size_t)b * HH * HH;
    __nv_bfloat16* Dh = dhi + (size_t)b * HH * HH;
    __nv_bfloat16* Dl = dlo + (size_t)b * HH * HH;
    int r0 = blockIdx.y * 32, c0 = blockIdx.x * 32;
    for (int rr = threadIdx.y; rr < 32; rr += 8)
        t[rr][threadIdx.x] = S[(size_t)(r0 + rr) * HH + c0 + threadIdx.x];
    __syncthreads();
    for (int rr = threadIdx.y; rr < 32; rr += 8) {
        float v = t[threadIdx.x][rr];
        size_t o = (size_t)(c0 + rr) * HH + r0 + threadIdx.x;
        split2(v, Dh[o], Dl[o]);
    }
}

// ---------------- HMMA split-bf16 GEMM (small Wc GEMM only) ----------------
#define ROWP 40
#define ROWB (ROWP*2)                  // 80 bytes
#define ARRB (128*ROWB)
#define STG3 (4*ARRB)
#define SMEM3 (2*STG3)

__global__ __launch_bounds__(256, 2)
void k_hmma3(const __nv_bfloat16* __restrict__ Ahi, const __nv_bfloat16* __restrict__ Alo,
             size_t strideA,
             const __nv_bfloat16* __restrict__ Bhi, const __nv_bfloat16* __restrict__ Blo,
             size_t strideB,
             float* __restrict__ C, size_t strideC,
             const float* __restrict__ bias, int Kd)
{
    extern __shared__ char smem[];
    const uint32_t sb = smem_u32(smem);
    const int tid = threadIdx.x;
    const int lane = tid & 31;
    const int warp = tid >> 5;
    const int wm = warp >> 2, wn = warp & 3;
    const int bat = blockIdx.z;
    const int m0 = blockIdx.y * 128;
    const int n0 = blockIdx.x * 128;

    const int r0 = tid >> 2, cj = tid & 3;
    const __nv_bfloat16* bAh = Ahi + (size_t)bat * strideA + (size_t)(m0 + r0) * Kd + cj * 8;
    const __nv_bfloat16* bAl = Alo + (size_t)bat * strideA + (size_t)(m0 + r0) * Kd + cj * 8;
    const __nv_bfloat16* bBh = Bhi + (size_t)bat * strideB + (size_t)(n0 + r0) * Kd + cj * 8;
    const __nv_bfloat16* bBl = Blo + (size_t)bat * strideB + (size_t)(n0 + r0) * Kd + cj * 8;
    const size_t rstep = (size_t)64 * Kd;
    const uint32_t d0 = (uint32_t)r0 * ROWB + (uint32_t)cj * 16;
    const uint32_t d1 = d0 + 64 * ROWB;

    float acc[4][4][4];
    #pragma unroll
    for (int mi = 0; mi < 4; mi++)
        #pragma unroll
        for (int ni = 0; ni < 4; ni++)
            #pragma unroll
            for (int j = 0; j < 4; j++) acc[mi][ni][j] = 0.f;

    const int nIt = Kd / 32;

#define LOAD3(it) do {                                            \
        uint32_t s_ = sb + ((it) & 1) * STG3;                     \
        int ko_ = (it) * 32;                                      \
        cp16(s_ + 0*ARRB + d0, bAh + ko_);                        \
        cp16(s_ + 0*ARRB + d1, bAh + rstep + ko_);                \
        cp16(s_ + 1*ARRB + d0, bAl + ko_);                        \
        cp16(s_ + 1*ARRB + d1, bAl + rstep + ko_);                \
        cp16(s_ + 2*ARRB + d0, bBh + ko_);                        \
        cp16(s_ + 2*ARRB + d1, bBh + rstep + ko_);                \
        cp16(s_ + 3*ARRB + d0, bBl + ko_);                        \
        cp16(s_ + 3*ARRB + d1, bBl + rstep + ko_);                \
        CP_COMMIT();                                              \
    } while (0)

    LOAD3(0);

    const int grp = lane >> 3, lr = lane & 7;
    const uint32_t aoff = (uint32_t)(wm * 64 + (grp & 1) * 8 + lr) * ROWB + (uint32_t)(grp >> 1) * 16;
    const uint32_t boff = (uint32_t)(wn * 32 + (grp >> 1) * 8 + lr) * ROWB + (uint32_t)(grp & 1) * 16;

    for (int it = 0; it < nIt; ++it) {
        CP_WAIT0();
        __syncthreads();
        if (it + 1 < nIt) LOAD3(it + 1);

        const uint32_t st = sb + (it & 1) * STG3;
        const uint32_t pAh = st + 0*ARRB + aoff;
        const uint32_t pAl = st + 1*ARRB + aoff;
        const uint32_t pBh = st + 2*ARRB + boff;
        const uint32_t pBl = st + 3*ARRB + boff;

        #pragma unroll
        for (int ks = 0; ks < 2; ks++) {
            const uint32_t kb2 = ks * 32;
            uint32_t ah[4][4], al[4][4];
            #pragma unroll
            for (int mi = 0; mi < 4; mi++) {
                ldsm4(ah[mi], pAh + (uint32_t)mi * (16 * ROWB) + kb2);
                ldsm4(al[mi], pAl + (uint32_t)mi * (16 * ROWB) + kb2);
            }
            #pragma unroll
            for (int pg = 0; pg < 2; pg++) {
                uint32_t bh[4], bl[4];
                ldsm4(bh, pBh + (uint32_t)pg * (16 * ROWB) + kb2);
                ldsm4(bl, pBl + (uint32_t)pg * (16 * ROWB) + kb2);
                #pragma unroll
                for (int mi = 0; mi < 4; mi++) {
                    mma16816(acc[mi][2*pg],   ah[mi], bh);
                    mma16816(acc[mi][2*pg+1], ah[mi], bh + 2);
                }
                #pragma unroll
                for (int mi = 0; mi < 4; mi++) {
                    mma16816(acc[mi][2*pg],   ah[mi], bl);
                    mma16816(acc[mi][2*pg+1], ah[mi], bl + 2);
                }
                #pragma unroll
                for (int mi = 0; mi < 4; mi++) {
                    mma16816(acc[mi][2*pg],   al[mi], bh);
                    mma16816(acc[mi][2*pg+1], al[mi], bh + 2);
                }
            }
        }
    }
#undef LOAD3

    const int r = lane >> 2, c2 = (lane & 3) * 2;
    const float* bb = bias ? (bias + (size_t)bat * HH) : nullptr;
    float* Cb = C + (size_t)bat * strideC;
    #pragma unroll
    for (int ni = 0; ni < 4; ni++) {
        int col = n0 + wn * 32 + ni * 8 + c2;
        float bx = bb ? bb[col] : 0.f;
        float by = bb ? bb[col + 1] : 0.f;
        #pragma unroll
        for (int mi = 0; mi < 4; mi++) {
            int row = m0 + wm * 64 + mi * 16 + r;
            float2 v0 = make_float2(acc[mi][ni][0] + bx, acc[mi][ni][1] + by);
            float2 v1 = make_float2(acc[mi][ni][2] + bx, acc[mi][ni][3] + by);
            *(float2*)(Cb + (size_t)row * HH + col) = v0;
            *(float2*)(Cb + (size_t)(row + 8) * HH + col) = v1;
        }
    }
}

// ---------------- fp16 2-product GEMM (big W_hs GEMM) ----------------
// C[m,n] = A[m,:]·B[n,:] + bias[n]; A = ah+al (fp16 pair), B = bh (fp16)
// BM=128, BN=128, BK=32; 8 warps 2x4; warp tile 64x32; 2-stage; occ 2; C fp16.
#define FA_H 0
#define FA_L ARRB
#define FB_H (2*ARRB)
#define FSTG (3*ARRB)                  // 30720
#define FSMEM (2*FSTG)                 // 61440

__global__ __launch_bounds__(256, 2)
void k_fgemm(const __half* __restrict__ Ah, const __half* __restrict__ Al,
             const __half* __restrict__ Bh,
             __half* __restrict__ C, const float* __restrict__ bias)
{
    extern __shared__ char smem[];
    const uint32_t sb = smem_u32(smem);
    const int tid = threadIdx.x;
    const int lane = tid & 31;
    const int warp = tid >> 5;
    const int wm = warp >> 2, wn = warp & 3;
    const int bat = blockIdx.z;
    const int m0 = blockIdx.y * 128;
    const int n0 = blockIdx.x * 128;

    // cp.async: 1536 16B chunks/stage = 6 per thread
    const __half* gsrc[6];
    uint32_t dsto[6];
    {
        const __half* bAh = Ah + (size_t)m0 * HH;
        const __half* bAl = Al + (size_t)m0 * HH;
        const __half* bBh = Bh + (size_t)bat * HH * HH + (size_t)n0 * HH;
        #pragma unroll
        for (int i = 0; i < 6; i++) {
            int id = i * 256 + tid;
            int cj = id & 3, rid = id >> 2;
            const __half* bp; uint32_t ao; int row;
            if (rid < 128)      { bp = bAh; ao = FA_H; row = rid; }
            else if (rid < 256) { bp = bAl; ao = FA_L; row = rid - 128; }
            else                { bp = bBh; ao = FB_H; row = rid - 256; }
            gsrc[i] = bp + (size_t)row * HH + cj * 8;
            dsto[i] = ao + (uint32_t)row * ROWB + (uint32_t)cj * 16;
        }
    }

    float acc[4][4][4];
    #pragma unroll
    for (int mi = 0; mi < 4; mi++)
        #pragma unroll
        for (int ni = 0; ni < 4; ni++)
            #pragma unroll
            for (int j = 0; j < 4; j++) acc[mi][ni][j] = 0.f;

    const int nIt = HH / 32;

#define FLOAD(it) do {                                        \
        uint32_t s_ = sb + ((it) & 1) * FSTG;                 \
        int ko_ = (it) * 32;                                  \
        _Pragma("unroll")                                     \
        for (int i_ = 0; i_ < 6; i_++)                        \
            cp16(s_ + dsto[i_], gsrc[i_] + ko_);              \
        CP_COMMIT();                                          \
    } while (0)

    FLOAD(0);

    const int grp = lane >> 3, lr = lane & 7;
    const uint32_t aoff = (uint32_t)(wm * 64 + (grp & 1) * 8 + lr) * ROWB + (uint32_t)(grp >> 1) * 16;
    const uint32_t boff = (uint32_t)(wn * 32 + (grp >> 1) * 8 + lr) * ROWB + (uint32_t)(grp & 1) * 16;

    for (int it = 0; it < nIt; ++it) {
        CP_WAIT0();
        __syncthreads();
        if (it + 1 < nIt) FLOAD(it + 1);

        const uint32_t st = sb + (it & 1) * FSTG;
        const uint32_t pAh = st + FA_H + aoff;
        const uint32_t pAl = st + FA_L + aoff;
        const uint32_t pBh = st + FB_H + boff;

        #pragma unroll
        for (int ks = 0; ks < 2; ks++) {
            const uint32_t kb2 = ks * 32;
            uint32_t ah[4][4], al[4][4];
            #pragma unroll
            for (int mi = 0; mi < 4; mi++) {
                ldsm4(ah[mi], pAh + (uint32_t)mi * (16 * ROWB) + kb2);
                ldsm4(al[mi], pAl + (uint32_t)mi * (16 * ROWB) + kb2);
            }
            #pragma unroll
            for (int pg = 0; pg < 2; pg++) {
                uint32_t bh[4];
                ldsm4(bh, pBh + (uint32_t)pg * (16 * ROWB) + kb2);
                #pragma unroll
                for (int mi = 0; mi < 4; mi++) {
                    mmaF16(acc[mi][2*pg],   ah[mi], bh);
                    mmaF16(acc[mi][2*pg+1], ah[mi], bh + 2);
                }
                #pragma unroll
                for (int mi = 0; mi < 4; mi++) {
                    mmaF16(acc[mi][2*pg],   al[mi], bh);
                    mmaF16(acc[mi][2*pg+1], al[mi], bh + 2);
                }
            }
        }
    }
#undef FLOAD

    // epilogue -> fp16
    const int r = lane >> 2, c2 = (lane & 3) * 2;
    const float* bb = bias + (size_t)bat * HH;
    __half* Cb = C + (size_t)bat * MROWS * HH;
    #pragma unroll
    for (int ni = 0; ni < 4; ni++) {
        int col = n0 + wn * 32 + ni * 8 + c2;
        float bx = bb[col], by = bb[col + 1];
        #pragma unroll
        for (int mi = 0; mi < 4; mi++) {
            int row = m0 + wm * 64 + mi * 16 + r;
            __half2 v0 = __floats2half2_rn(acc[mi][ni][0] + bx, acc[mi][ni][1] + by);
            __half2 v1 = __floats2half2_rn(acc[mi][ni][2] + bx, acc[mi][ni][3] + by);
            *(__half2*)(Cb + (size_t)row * HH + col) = v0;
            *(__half2*)(Cb + (size_t)(row + 8) * HH + col) = v1;
        }
    }
}

// ---------------- prologue: qbuf = question, h = 0 ----------------
__global__ void k_prologue(const float* __restrict__ question) {
    int t = blockIdx.x * 256 + threadIdx.x;
    if (t < BB*HH) { g_qbuf[t] = question[t]; g_hbuf[t] = 0.f; }
}

// ---------------- combined bias: bc[k][j] = pw_b[k] @ Ws_W[k] + Ws_b[k] ----------------
__global__ void k_bc(const float* __restrict__ pw_b, const float* __restrict__ Ws_W,
                     const float* __restrict__ Ws_b) {
    int k = blockIdx.x;
    int j = blockIdx.y * 256 + threadIdx.x;
    float acc = Ws_b[k*HH + j];
    const float* W = Ws_W + (size_t)k*HH*HH;
    const float* b = pw_b + k*HH;
    #pragma unroll 4
    for (int m = 0; m < HH; m++) acc = fmaf(b[m], W[(size_t)m*HH + j], acc);
    g_bc[k*HH + j] = acc;
}

// ---------------- W_ht = qbuf @ Wt_W[k] + Wt_b[k]  (k-split, atomic) ----------------
__global__ void k_init_wht(const float* __restrict__ Wt_b) {
    int t = blockIdx.x * 256 + threadIdx.x;
    if (t < KK*BB*HH) {
        int k = t / (BB*HH);
        int j = t % HH;
        g_Wht[t] = Wt_b[k*HH + j];
    }
}

__global__ void k_wht(const float* __restrict__ Wt_W) {
    int k  = blockIdx.x;
    int jc = blockIdx.y;
    int hs = blockIdx.z;
    int t  = threadIdx.x;
    int j  = jc*128 + t;
    int h0 = hs*128;
    __shared__ float qs[32][128];
    #pragma unroll 8
    for (int r = 0; r < 32; r++) qs[r][t] = g_qbuf[r*HH + h0 + t];
    __syncthreads();
    float acc[32];
    #pragma unroll
    for (int b = 0; b < 32; b++) acc[b] = 0.f;
    for (int hh = 0; hh < 128; hh++) {
        float w = Wt_W[((size_t)k*HH + h0 + hh)*HH + j];
        #pragma unroll
        for (int b = 0; b < 32; b++) acc[b] = fmaf(qs[b][hh], w, acc[b]);
    }
    #pragma unroll
    for (int b = 0; b < 32; b++) atomicAdd(&g_Wht[(k*BB + b)*HH + j], acc[b]);
}

// ---------------- scores[k,b,s] = We . tanh(W_hs + W_ht) + We_b ----------------
__global__ __launch_bounds__(256)
void k_scores(const float* __restrict__ WeW, const float* __restrict__ Web) {
    int kb = blockIdx.x;
    int sc = blockIdx.y;
    int k = kb / BB;
    __shared__ float4 shW[HH/4];
    __shared__ float4 shE[HH/4];
    if (threadIdx.x < HH/4) {
        shW[threadIdx.x] = ((const float4*)(g_Wht + (size_t)kb*HH))[threadIdx.x];
        shE[threadIdx.x] = ((const float4*)(WeW + (size_t)k*HH))[threadIdx.x];
    }
    __syncthreads();
    int warp = threadIdx.x >> 5, lane = threadIdx.x & 31;
    float web = Web[k];
    for (int s = sc*128 + warp; s < sc*128 + 128; s += 8) {
        const uint4* row = (const uint4*)(g_Whs + ((size_t)kb*SS + s)*HH);
        float sum = 0.f;
        #pragma unroll
        for (int i = 0; i < 3; i++) {
            int idx = lane + i*32;            // 0..95, 8 halves each
            uint4 raw = row[idx];
            const __half2* hp = (const __half2*)&raw;
            float2 f0 = __half22float2(hp[0]);
            float2 f1 = __half22float2(hp[1]);
            float2 f2 = __half22float2(hp[2]);
            float2 f3 = __half22float2(hp[3]);
            float4 wa = shW[2*idx],   wbv = shW[2*idx+1];
            float4 ea = shE[2*idx],   ebv = shE[2*idx+1];
            float x0 = f0.x + wa.x, x1 = f0.y + wa.y, x2 = f1.x + wa.z, x3 = f1.y + wa.w;
            float x4 = f2.x + wbv.x, x5 = f2.y + wbv.y, x6 = f3.x + wbv.z, x7 = f3.y + wbv.w;
            float t0 = 1.f - __fdividef(2.f, __expf(2.f*x0) + 1.f);
            float t1 = 1.f - __fdividef(2.f, __expf(2.f*x1) + 1.f);
            float t2 = 1.f - __fdividef(2.f, __expf(2.f*x2) + 1.f);
            float t3 = 1.f - __fdividef(2.f, __expf(2.f*x3) + 1.f);
            float t4 = 1.f - __fdividef(2.f, __expf(2.f*x4) + 1.f);
            float t5 = 1.f - __fdividef(2.f, __expf(2.f*x5) + 1.f);
            float t6 = 1.f - __fdividef(2.f, __expf(2.f*x6) + 1.f);
            float t7 = 1.f - __fdividef(2.f, __expf(2.f*x7) + 1.f);
            sum = fmaf(t0, ea.x, sum); sum = fmaf(t1, ea.y, sum);
            sum = fmaf(t2, ea.z, sum); sum = fmaf(t3, ea.w, sum);
            sum = fmaf(t4, ebv.x, sum); sum = fmaf(t5, ebv.y, sum);
            sum = fmaf(t6, ebv.z, sum); sum = fmaf(t7, ebv.w, sum);
        }
        #pragma unroll
        for (int o = 16; o; o >>= 1) sum += __shfl_xor_sync(0xffffffffu, sum, o);
        if (lane == 0) g_scores[kb*SS + s] = sum + web;
    }
}

// ---------------- softmax over S, in place ----------------
__global__ void k_softmax() {
    __shared__ float red[256];
    int row = blockIdx.x;
    float* p = g_scores + (size_t)row * SS;
    int t = threadIdx.x;
    float a = p[t], b = p[t + 256];
    red[t] = fmaxf(a, b);
    __syncthreads();
    for (int o = 128; o; o >>= 1) { if (t < o) red[t] = fmaxf(red[t], red[t+o]); __syncthreads(); }
    float m = red[0];
    __syncthreads();
    float e0 = __expf(a - m), e1 = __expf(b - m);
    red[t] = e0 + e1;
    __syncthreads();
    for (int o = 128; o; o >>= 1) { if (t < o) red[t] += red[t+o]; __syncthreads(); }
    float inv = 1.f / red[0];
    p[t] = e0 * inv;
    p[t + 256] = e1 * inv;
}

// ---------------- alpha_linear, prob (hop 0), argmax ----------------
__global__ void k_alpha(const float* __restrict__ hw, const float* __restrict__ hb,
                        float* __restrict__ out_prob, int hop) {
    int b = blockIdx.x;
    int s = threadIdx.x;
    float al = hb[0];
    #pragma unroll
    for (int k = 0; k < KK; k++) al = fmaf(g_scores[(k*BB + b)*SS + s], hw[k], al);
    __shared__ float ssq[512];
    __shared__ float sval[512];
    __shared__ int   sidx[512];
    ssq[s] = al * al; sval[s] = al; sidx[s] = s;
    __syncthreads();
    for (int o = 256; o; o >>= 1) {
        if (s < o) {
            ssq[s] += ssq[s + o];
            float v2 = sval[s + o]; int i2 = sidx[s + o];
            if (v2 > sval[s] || (v2 == sval[s] && i2 < sidx[s])) { sval[s] = v2; sidx[s] = i2; }
        }
        __syncthreads();
    }
    if (s == 0) g_idx[b] = sidx[0];
    if (hop == 0) out_prob[b*SS + s] = al / sqrtf(ssq[0]);
}

// ---------------- GRU ----------------
__global__ void k_gru_init(const float* __restrict__ bih, const float* __restrict__ bhh) {
    int t = blockIdx.x * 256 + threadIdx.x;
    if (t < BB*H3) { int j = t % H3; g_GX[t] = bih[j]; g_GH[t] = bhh[j]; }
}

__global__ void k_grugemm(const float* __restrict__ Wih, const float* __restrict__ Whh,
                          const float* __restrict__ text) {
    int jc = blockIdx.x;
    int ks = blockIdx.y;
    int bg = blockIdx.z;
    int t = threadIdx.x;
    int j = jc*256 + t;
    int i0 = ks*256;
    __shared__ float xs[8][256];
    int i = i0 + t;
    #pragma unroll
    for (int r = 0; r < 8; r++) {
        int b = bg*8 + r;
        float v;
        if (i < 768)       v = g_qbuf[b*HH + i];
        else if (i < 1536) v = text[((size_t)b*SS + g_idx[b])*HH + (i - 768)];
        else               v = g_hbuf[b*HH + (i - 1536)];
        xs[r][t] = v;
    }
    __syncthreads();
    const float* W; int wi0; float* G;
    if (i0 < 1536) { W = Wih; wi0 = i0;        G = g_GX; }
    else           { W = Whh; wi0 = i0 - 1536; G = g_GH; }
    float acc[8];
    #pragma unroll
    for (int r = 0; r < 8; r++) acc[r] = 0.f;
    #pragma unroll 4
    for (int kk = 0; kk < 256; kk++) {
        float w = W[(size_t)(wi0 + kk)*H3 + j];
        #pragma unroll
        for (int r = 0; r < 8; r++) acc[r] = fmaf(xs[r][kk], w, acc[r]);
    }
    #pragma unroll
    for (int r = 0; r < 8; r++) atomicAdd(&G[(bg*8 + r)*H3 + j], acc[r]);
}

__global__ void k_grugate(float* __restrict__ out_h, int hop) {
    int t = blockIdx.x * 256 + threadIdx.x;
    if (t >= BB*HH) return;
    int b = t / HH, j = t % HH;
    float gxr = g_GX[b*H3 + j],        ghr = g_GH[b*H3 + j];
    float gxz = g_GX[b*H3 + HH + j],   ghz = g_GH[b*H3 + HH + j];
    float gxn = g_GX[b*H3 + 2*HH + j], ghn = g_GH[b*H3 + 2*HH + j];
    float r = 1.f / (1.f + expf(-(gxr + ghr)));
    float z = 1.f / (1.f + expf(-(gxz + ghz)));
    float n = tanhf(gxn + r * ghn);
    float hprev = g_hbuf[t];
    float hn = (1.f - z) * n + z * hprev;
    g_hbuf[t] = hn;
    g_qbuf[t] = hn;
    out_h[((size_t)b*HOPS + hop)*HH + j] = hn;
}

// ---------------- launch ----------------
extern "C" void kernel_launch(void* const* d_in, const int* in_sizes, int n_in,
                              void* d_out, int out_size) {
    const float* question = (const float*)d_in[0];
    const float* text     = (const float*)d_in[1];
    const float* pw_W     = (const float*)d_in[2];
    const float* pw_b     = (const float*)d_in[3];
    const float* Ws_W     = (const float*)d_in[4];
    const float* Ws_b     = (const float*)d_in[5];
    const float* Wt_W     = (const float*)d_in[6];
    const float* Wt_b     = (const float*)d_in[7];
    const float* We_W     = (const float*)d_in[8];
    const float* We_b     = (const float*)d_in[9];
    const float* headw_W  = (const float*)d_in[10];
    const float* headw_b  = (const float*)d_in[11];
    const float* gru_Wih  = (const float*)d_in[12];
    const float* gru_Whh  = (const float*)d_in[13];
    const float* gru_bih  = (const float*)d_in[14];
    const float* gru_bhh  = (const float*)d_in[15];

    float* out_prob = (float*)d_out;
    float* out_h    = (float*)d_out + BB*SS;

    float *p_WcT, *p_bc;
    __half *p_Whs, *p_tAh, *p_tAl, *p_Bh;
    __nv_bfloat16 *p_pwhi, *p_pwlo, *p_WsThi, *p_WsTlo;
    cudaGetSymbolAddress((void**)&p_WcT,   g_WcT);
    cudaGetSymbolAddress((void**)&p_bc,    g_bc);
    cudaGetSymbolAddress((void**)&p_Whs,   g_Whs);
    cudaGetSymbolAddress((void**)&p_tAh,   g_tAh);
    cudaGetSymbolAddress((void**)&p_tAl,   g_tAl);
    cudaGetSymbolAddress((void**)&p_Bh,    g_Bh);
    cudaGetSymbolAddress((void**)&p_pwhi,  g_pwhi);
    cudaGetSymbolAddress((void**)&p_pwlo,  g_pwlo);
    cudaGetSymbolAddress((void**)&p_WsThi, g_WsThi);
    cudaGetSymbolAddress((void**)&p_WsTlo, g_WsTlo);

    cudaFuncSetAttribute(k_hmma3, cudaFuncAttributeMaxDynamicSharedMemorySize, SMEM3);
    cudaFuncSetAttribute(k_fgemm, cudaFuncAttributeMaxDynamicSharedMemorySize, FSMEM);

    k_prologue<<<(BB*HH + 255)/256, 256>>>(question);
    k_bc<<<dim3(KK, HH/256), 256>>>(pw_b, Ws_W, Ws_b);

    // fp16 split of text (A operand)
    k_splitH<<<(MROWS*HH + 255)/256, 256>>>(text, p_tAh, p_tAl, MROWS*HH);

    // bf16 splits for the small Wc GEMM
    k_split<<<(KK*HH*HH + 255)/256, 256>>>(pw_W, p_pwhi, p_pwlo, KK*HH*HH);
    k_splitT<<<dim3(HH/32, HH/32, KK), dim3(32, 8)>>>(Ws_W, p_WsThi, p_WsTlo);

    // WcT[k] = WsT[k] (.) pw[k]  ->  WcT rows = output cols (operand swap)
    k_hmma3<<<dim3(HH/128, HH/128, KK), 256, SMEM3>>>(
        p_WsThi, p_WsTlo, (size_t)HH*HH,
        p_pwhi, p_pwlo, (size_t)HH*HH,
        p_WcT, (size_t)HH*HH, nullptr, HH);

    // WcT -> fp16 (B operand)
    k_cvtH<<<(KK*HH*HH + 255)/256, 256>>>(p_WcT, p_Bh, KK*HH*HH);

    // W_hs[k] = text @ Wc[k] + bc[k]  (fp16 2-product HMMA), output fp16
    k_fgemm<<<dim3(HH/128, MROWS/128, KK), 256, FSMEM>>>(
        p_tAh, p_tAl, p_Bh, p_Whs, p_bc);

    for (int hop = 0; hop < HOPS; hop++) {
        k_init_wht<<<(KK*BB*HH + 255)/256, 256>>>(Wt_b);
        k_wht<<<dim3(KK, HH/128, HH/128), 128>>>(Wt_W);
        k_scores<<<dim3(KK*BB, SS/128), 256>>>(We_W, We_b);
        k_softmax<<<KK*BB, 256>>>();
        k_alpha<<<BB, 512>>>(headw_W, headw_b, out_prob, hop);
        k_gru_init<<<(BB*H3 + 255)/256, 256>>>(gru_bih, gru_bhh);
        k_grugemm<<<dim3(H3/256, H3/256, BB/8), 256>>>(gru_Wih, gru_Whh, text);
        k_grugate<<<(BB*HH + 255)/256, 256>>>(out_h, hop);
    }
}

// round 11
// speedup vs baseline: 2.8433x; 1.3225x over previous
#include <cuda_runtime.h>
#include <cuda_bf16.h>
#include <cuda_fp16.h>
#include <math.h>
#include <stdint.h>

#define BB 32
#define SS 512
#define HH 768
#define KK 4
#define HOPS 3
#define H2 1536
#define H3 2304
#define MROWS (BB*SS)

// ---------------- scratch (device globals; no allocation) ----------------
__device__ float g_WcT[(size_t)KK*HH*HH];          // Wc^T fp32 [k][j][i]
__device__ float g_bc[KK*HH];
__device__ __half g_Whs[(size_t)KK*MROWS*HH];      // [K,B,S,H] fp16 100MB
__device__ float g_Wht[KK*BB*HH];
__device__ float g_scores[KK*BB*SS];
__device__ float g_qbuf[BB*HH];
__device__ float g_hbuf[BB*HH];
__device__ float g_GX[BB*H3];
__device__ float g_GH[BB*H3];
__device__ int   g_idx[BB];
// bf16 splits for the small Wc GEMM
__device__ __nv_bfloat16 g_pwhi[(size_t)KK*HH*HH];
__device__ __nv_bfloat16 g_pwlo[(size_t)KK*HH*HH];
__device__ __nv_bfloat16 g_WsThi[(size_t)KK*HH*HH];
__device__ __nv_bfloat16 g_WsTlo[(size_t)KK*HH*HH];
// fp16 operands for the big GEMM
__device__ __half g_tAh[(size_t)MROWS*HH];
__device__ __half g_Bh[(size_t)KK*HH*HH];

// ---------------- helpers ----------------
namespace mhk {
__device__ __forceinline__ uint32_t smem_u32(const void* p) {
    uint32_t a;
    asm("{ .reg .u64 t; cvta.to.shared.u64 t, %1; cvt.u32.u64 %0, t; }" : "=r"(a) : "l"(p));
    return a;
}
__device__ __forceinline__ void mma16816(float* d, const uint32_t* a, const uint32_t* b) {
    asm volatile("mma.sync.aligned.m16n8k16.row.col.f32.bf16.bf16.f32 "
        "{%0,%1,%2,%3},{%4,%5,%6,%7},{%8,%9},{%0,%1,%2,%3};"
        : "+f"(d[0]), "+f"(d[1]), "+f"(d[2]), "+f"(d[3])
        : "r"(a[0]), "r"(a[1]), "r"(a[2]), "r"(a[3]), "r"(b[0]), "r"(b[1]));
}
__device__ __forceinline__ void mmaF16(float* d, const uint32_t* a, const uint32_t* b) {
    asm volatile("mma.sync.aligned.m16n8k16.row.col.f32.f16.f16.f32 "
        "{%0,%1,%2,%3},{%4,%5,%6,%7},{%8,%9},{%0,%1,%2,%3};"
        : "+f"(d[0]), "+f"(d[1]), "+f"(d[2]), "+f"(d[3])
        : "r"(a[0]), "r"(a[1]), "r"(a[2]), "r"(a[3]), "r"(b[0]), "r"(b[1]));
}
__device__ __forceinline__ void ldsm4(uint32_t* r, uint32_t addr) {
    asm volatile("ldmatrix.sync.aligned.m8n8.x4.shared.b16 {%0,%1,%2,%3}, [%4];"
        : "=r"(r[0]), "=r"(r[1]), "=r"(r[2]), "=r"(r[3]) : "r"(addr));
}
__device__ __forceinline__ void cp16(uint32_t dst, const void* src) {
    asm volatile("cp.async.cg.shared.global [%0], [%1], 16;" :: "r"(dst), "l"(src));
}
__device__ __forceinline__ __half2 tanh2f(__half2 x) {
    uint32_t xi = *(const uint32_t*)&x, r;
    asm("tanh.approx.f16x2 %0, %1;" : "=r"(r) : "r"(xi));
    return *(__half2*)&r;
}
} // namespace mhk
using mhk::smem_u32; using mhk::mma16816; using mhk::mmaF16;
using mhk::ldsm4; using mhk::cp16;

#define CP_COMMIT() asm volatile("cp.async.commit_group;" ::: "memory")
#define CP_WAIT0()  asm volatile("cp.async.wait_group 0;" ::: "memory")
#define CP_WAIT1()  asm volatile("cp.async.wait_group 1;" ::: "memory")

// ---------------- split helpers ----------------
__device__ __forceinline__ void split2(float x, __nv_bfloat16& h, __nv_bfloat16& l) {
    __nv_bfloat16 hb = __float2bfloat16(x);
    h = hb;
    l = __float2bfloat16(x - __bfloat162float(hb));
}

__global__ void k_split(const float* __restrict__ src, __nv_bfloat16* __restrict__ dhi,
                        __nv_bfloat16* __restrict__ dlo, int n) {
    int i = blockIdx.x * 256 + threadIdx.x;
    if (i < n) split2(src[i], dhi[i], dlo[i]);
}

// fp32 -> fp16 single
__global__ void k_cvtH(const float* __restrict__ src, __half* __restrict__ dst, int n) {
    int i = blockIdx.x * 256 + threadIdx.x;
    if (i < n) dst[i] = __float2half_rn(src[i]);
}

// transpose + split: src [R=768, C=768] per batch -> dst [C, R]
__global__ void k_splitT(const float* __restrict__ src, __nv_bfloat16* __restrict__ dhi,
                         __nv_bfloat16* __restrict__ dlo) {
    __shared__ float t[32][33];
    int b = blockIdx.z;
    const float* S = src + (size_t)b * HH * HH;
    __nv_bfloat16* Dh = dhi + (size_t)b * HH * HH;
    __nv_bfloat16* Dl = dlo + (size_t)b * HH * HH;
    int r0 = blockIdx.y * 32, c0 = blockIdx.x * 32;
    for (int rr = threadIdx.y; rr < 32; rr += 8)
        t[rr][threadIdx.x] = S[(size_t)(r0 + rr) * HH + c0 + threadIdx.x];
    __syncthreads();
    for (int rr = threadIdx.y; rr < 32; rr += 8) {
        float v = t[threadIdx.x][rr];
        size_t o = (size_t)(c0 + rr) * HH + r0 + threadIdx.x;
        split2(v, Dh[o], Dl[o]);
    }
}

// ---------------- HMMA split-bf16 GEMM (small Wc GEMM only) ----------------
#define ROWP 40
#define ROWB (ROWP*2)                  // 80 bytes
#define ARRB (128*ROWB)
#define STG3 (4*ARRB)
#define SMEM3 (2*STG3)

__global__ __launch_bounds__(256, 2)
void k_hmma3(const __nv_bfloat16* __restrict__ Ahi, const __nv_bfloat16* __restrict__ Alo,
             size_t strideA,
             const __nv_bfloat16* __restrict__ Bhi, const __nv_bfloat16* __restrict__ Blo,
             size_t strideB,
             float* __restrict__ C, size_t strideC,
             const float* __restrict__ bias, int Kd)
{
    extern __shared__ char smem[];
    const uint32_t sb = smem_u32(smem);
    const int tid = threadIdx.x;
    const int lane = tid & 31;
    const int warp = tid >> 5;
    const int wm = warp >> 2, wn = warp & 3;
    const int bat = blockIdx.z;
    const int m0 = blockIdx.y * 128;
    const int n0 = blockIdx.x * 128;

    const int r0 = tid >> 2, cj = tid & 3;
    const __nv_bfloat16* bAh = Ahi + (size_t)bat * strideA + (size_t)(m0 + r0) * Kd + cj * 8;
    const __nv_bfloat16* bAl = Alo + (size_t)bat * strideA + (size_t)(m0 + r0) * Kd + cj * 8;
    const __nv_bfloat16* bBh = Bhi + (size_t)bat * strideB + (size_t)(n0 + r0) * Kd + cj * 8;
    const __nv_bfloat16* bBl = Blo + (size_t)bat * strideB + (size_t)(n0 + r0) * Kd + cj * 8;
    const size_t rstep = (size_t)64 * Kd;
    const uint32_t d0 = (uint32_t)r0 * ROWB + (uint32_t)cj * 16;
    const uint32_t d1 = d0 + 64 * ROWB;

    float acc[4][4][4];
    #pragma unroll
    for (int mi = 0; mi < 4; mi++)
        #pragma unroll
        for (int ni = 0; ni < 4; ni++)
            #pragma unroll
            for (int j = 0; j < 4; j++) acc[mi][ni][j] = 0.f;

    const int nIt = Kd / 32;

#define LOAD3(it) do {                                            \
        uint32_t s_ = sb + ((it) & 1) * STG3;                     \
        int ko_ = (it) * 32;                                      \
        cp16(s_ + 0*ARRB + d0, bAh + ko_);                        \
        cp16(s_ + 0*ARRB + d1, bAh + rstep + ko_);                \
        cp16(s_ + 1*ARRB + d0, bAl + ko_);                        \
        cp16(s_ + 1*ARRB + d1, bAl + rstep + ko_);                \
        cp16(s_ + 2*ARRB + d0, bBh + ko_);                        \
        cp16(s_ + 2*ARRB + d1, bBh + rstep + ko_);                \
        cp16(s_ + 3*ARRB + d0, bBl + ko_);                        \
        cp16(s_ + 3*ARRB + d1, bBl + rstep + ko_);                \
        CP_COMMIT();                                              \
    } while (0)

    LOAD3(0);

    const int grp = lane >> 3, lr = lane & 7;
    const uint32_t aoff = (uint32_t)(wm * 64 + (grp & 1) * 8 + lr) * ROWB + (uint32_t)(grp >> 1) * 16;
    const uint32_t boff = (uint32_t)(wn * 32 + (grp >> 1) * 8 + lr) * ROWB + (uint32_t)(grp & 1) * 16;

    for (int it = 0; it < nIt; ++it) {
        CP_WAIT0();
        __syncthreads();
        if (it + 1 < nIt) LOAD3(it + 1);

        const uint32_t st = sb + (it & 1) * STG3;
        const uint32_t pAh = st + 0*ARRB + aoff;
        const uint32_t pAl = st + 1*ARRB + aoff;
        const uint32_t pBh = st + 2*ARRB + boff;
        const uint32_t pBl = st + 3*ARRB + boff;

        #pragma unroll
        for (int ks = 0; ks < 2; ks++) {
            const uint32_t kb2 = ks * 32;
            uint32_t ah[4][4], al[4][4];
            #pragma unroll
            for (int mi = 0; mi < 4; mi++) {
                ldsm4(ah[mi], pAh + (uint32_t)mi * (16 * ROWB) + kb2);
                ldsm4(al[mi], pAl + (uint32_t)mi * (16 * ROWB) + kb2);
            }
            #pragma unroll
            for (int pg = 0; pg < 2; pg++) {
                uint32_t bh[4], bl[4];
                ldsm4(bh, pBh + (uint32_t)pg * (16 * ROWB) + kb2);
                ldsm4(bl, pBl + (uint32_t)pg * (16 * ROWB) + kb2);
                #pragma unroll
                for (int mi = 0; mi < 4; mi++) {
                    mma16816(acc[mi][2*pg],   ah[mi], bh);
                    mma16816(acc[mi][2*pg+1], ah[mi], bh + 2);
                }
                #pragma unroll
                for (int mi = 0; mi < 4; mi++) {
                    mma16816(acc[mi][2*pg],   ah[mi], bl);
                    mma16816(acc[mi][2*pg+1], ah[mi], bl + 2);
                }
                #pragma unroll
                for (int mi = 0; mi < 4; mi++) {
                    mma16816(acc[mi][2*pg],   al[mi], bh);
                    mma16816(acc[mi][2*pg+1], al[mi], bh + 2);
                }
            }
        }
    }
#undef LOAD3

    const int r = lane >> 2, c2 = (lane & 3) * 2;
    const float* bb = bias ? (bias + (size_t)bat * HH) : nullptr;
    float* Cb = C + (size_t)bat * strideC;
    #pragma unroll
    for (int ni = 0; ni < 4; ni++) {
        int col = n0 + wn * 32 + ni * 8 + c2;
        float bx = bb ? bb[col] : 0.f;
        float by = bb ? bb[col + 1] : 0.f;
        #pragma unroll
        for (int mi = 0; mi < 4; mi++) {
            int row = m0 + wm * 64 + mi * 16 + r;
            float2 v0 = make_float2(acc[mi][ni][0] + bx, acc[mi][ni][1] + by);
            float2 v1 = make_float2(acc[mi][ni][2] + bx, acc[mi][ni][3] + by);
            *(float2*)(Cb + (size_t)row * HH + col) = v0;
            *(float2*)(Cb + (size_t)(row + 8) * HH + col) = v1;
        }
    }
}

// ---------------- fp16 single-product GEMM (big W_hs GEMM) ----------------
// C[m,n] = A[m,:]·B[n,:] + bias[n]; A, B fp16. BM=128, BN=128, BK=32;
// 8 warps 2x4; warp tile 64x32; 3-stage cp.async; occ 2; C fp16.
#define F2STG (2*ARRB)                 // 20480
#define F2SMEM (3*F2STG)               // 61440

__global__ __launch_bounds__(256, 2)
void k_fgemm2(const __half* __restrict__ Ah, const __half* __restrict__ Bh,
              __half* __restrict__ C, const float* __restrict__ bias)
{
    extern __shared__ char smem[];
    const uint32_t sb = smem_u32(smem);
    const int tid = threadIdx.x;
    const int lane = tid & 31;
    const int warp = tid >> 5;
    const int wm = warp >> 2, wn = warp & 3;
    const int bat = blockIdx.z;
    const int m0 = blockIdx.y * 128;
    const int n0 = blockIdx.x * 128;

    // cp.async: 1024 16B chunks/stage = 4 per thread
    const __half* gsrc[4];
    uint32_t dsto[4];
    {
        const __half* bA = Ah + (size_t)m0 * HH;
        const __half* bB = Bh + (size_t)bat * HH * HH + (size_t)n0 * HH;
        #pragma unroll
        for (int i = 0; i < 4; i++) {
            int id = i * 256 + tid;
            int cj = id & 3, rid = id >> 2;        // rid 0..255
            const __half* bp; uint32_t ao; int row;
            if (rid < 128) { bp = bA; ao = 0;    row = rid; }
            else           { bp = bB; ao = ARRB; row = rid - 128; }
            gsrc[i] = bp + (size_t)row * HH + cj * 8;
            dsto[i] = ao + (uint32_t)row * ROWB + (uint32_t)cj * 16;
        }
    }

    float acc[4][4][4];
    #pragma unroll
    for (int mi = 0; mi < 4; mi++)
        #pragma unroll
        for (int ni = 0; ni < 4; ni++)
            #pragma unroll
            for (int j = 0; j < 4; j++) acc[mi][ni][j] = 0.f;

    const int nIt = HH / 32;

#define F2LOAD(it) do {                                       \
        uint32_t s_ = sb + ((it) % 3) * F2STG;                \
        int ko_ = (it) * 32;                                  \
        _Pragma("unroll")                                     \
        for (int i_ = 0; i_ < 4; i_++)                        \
            cp16(s_ + dsto[i_], gsrc[i_] + ko_);              \
        CP_COMMIT();                                          \
    } while (0)

    F2LOAD(0);
    F2LOAD(1);

    const int grp = lane >> 3, lr = lane & 7;
    const uint32_t aoff = (uint32_t)(wm * 64 + (grp & 1) * 8 + lr) * ROWB + (uint32_t)(grp >> 1) * 16;
    const uint32_t boff = (uint32_t)(wn * 32 + (grp >> 1) * 8 + lr) * ROWB + (uint32_t)(grp & 1) * 16;

    for (int it = 0; it < nIt; ++it) {
        CP_WAIT1();
        __syncthreads();
        if (it + 2 < nIt) F2LOAD(it + 2);

        const uint32_t st = sb + (it % 3) * F2STG;
        const uint32_t pA = st + aoff;
        const uint32_t pB = st + ARRB + boff;

        #pragma unroll
        for (int ks = 0; ks < 2; ks++) {
            const uint32_t kb2 = ks * 32;
            uint32_t ah[4][4];
            #pragma unroll
            for (int mi = 0; mi < 4; mi++)
                ldsm4(ah[mi], pA + (uint32_t)mi * (16 * ROWB) + kb2);
            #pragma unroll
            for (int pg = 0; pg < 2; pg++) {
                uint32_t bh[4];
                ldsm4(bh, pB + (uint32_t)pg * (16 * ROWB) + kb2);
                #pragma unroll
                for (int mi = 0; mi < 4; mi++) {
                    mmaF16(acc[mi][2*pg],   ah[mi], bh);
                    mmaF16(acc[mi][2*pg+1], ah[mi], bh + 2);
                }
            }
        }
    }
#undef F2LOAD

    // epilogue -> fp16
    const int r = lane >> 2, c2 = (lane & 3) * 2;
    const float* bb = bias + (size_t)bat * HH;
    __half* Cb = C + (size_t)bat * MROWS * HH;
    #pragma unroll
    for (int ni = 0; ni < 4; ni++) {
        int col = n0 + wn * 32 + ni * 8 + c2;
        float bx = bb[col], by = bb[col + 1];
        #pragma unroll
        for (int mi = 0; mi < 4; mi++) {
            int row = m0 + wm * 64 + mi * 16 + r;
            __half2 v0 = __floats2half2_rn(acc[mi][ni][0] + bx, acc[mi][ni][1] + by);
            __half2 v1 = __floats2half2_rn(acc[mi][ni][2] + bx, acc[mi][ni][3] + by);
            *(__half2*)(Cb + (size_t)row * HH + col) = v0;
            *(__half2*)(Cb + (size_t)(row + 8) * HH + col) = v1;
        }
    }
}

// ---------------- prologue: qbuf = question, h = 0 ----------------
__global__ void k_prologue(const float* __restrict__ question) {
    int t = blockIdx.x * 256 + threadIdx.x;
    if (t < BB*HH) { g_qbuf[t] = question[t]; g_hbuf[t] = 0.f; }
}

// ---------------- combined bias: bc[k][j] = pw_b[k] @ Ws_W[k] + Ws_b[k] ----------------
__global__ void k_bc(const float* __restrict__ pw_b, const float* __restrict__ Ws_W,
                     const float* __restrict__ Ws_b) {
    int k = blockIdx.x;
    int j = blockIdx.y * 256 + threadIdx.x;
    float acc = Ws_b[k*HH + j];
    const float* W = Ws_W + (size_t)k*HH*HH;
    const float* b = pw_b + k*HH;
    #pragma unroll 4
    for (int m = 0; m < HH; m++) acc = fmaf(b[m], W[(size_t)m*HH + j], acc);
    g_bc[k*HH + j] = acc;
}

// ---------------- W_ht = qbuf @ Wt_W[k] + Wt_b[k]  (k-split, atomic) ----------------
__global__ void k_init_wht(const float* __restrict__ Wt_b) {
    int t = blockIdx.x * 256 + threadIdx.x;
    if (t < KK*BB*HH) {
        int k = t / (BB*HH);
        int j = t % HH;
        g_Wht[t] = Wt_b[k*HH + j];
    }
}

__global__ void k_wht(const float* __restrict__ Wt_W) {
    int k  = blockIdx.x;
    int jc = blockIdx.y;
    int hs = blockIdx.z;
    int t  = threadIdx.x;
    int j  = jc*128 + t;
    int h0 = hs*128;
    __shared__ float qs[32][128];
    #pragma unroll 8
    for (int r = 0; r < 32; r++) qs[r][t] = g_qbuf[r*HH + h0 + t];
    __syncthreads();
    float acc[32];
    #pragma unroll
    for (int b = 0; b < 32; b++) acc[b] = 0.f;
    for (int hh = 0; hh < 128; hh++) {
        float w = Wt_W[((size_t)k*HH + h0 + hh)*HH + j];
        #pragma unroll
        for (int b = 0; b < 32; b++) acc[b] = fmaf(qs[b][hh], w, acc[b]);
    }
    #pragma unroll
    for (int b = 0; b < 32; b++) atomicAdd(&g_Wht[(k*BB + b)*HH + j], acc[b]);
}

// ---------------- scores[k,b,s] = We . tanh(W_hs + W_ht) + We_b ----------------
// fp16x2 pipeline: HADD2 + tanh.approx.f16x2 + HFMA2, fp32 cross-lane reduce.
__global__ __launch_bounds__(256)
void k_scores(const float* __restrict__ WeW, const float* __restrict__ Web) {
    int kb = blockIdx.x;
    int sc = blockIdx.y;
    int k = kb / BB;
    __shared__ __half2 shW[HH/2];
    __shared__ __half2 shE[HH/2];
    for (int i = threadIdx.x; i < HH/2; i += 256) {
        float2 w = ((const float2*)(g_Wht + (size_t)kb*HH))[i];
        float2 e = ((const float2*)(WeW + (size_t)k*HH))[i];
        shW[i] = __floats2half2_rn(w.x, w.y);
        shE[i] = __floats2half2_rn(e.x, e.y);
    }
    __syncthreads();
    int warp = threadIdx.x >> 5, lane = threadIdx.x & 31;
    float web = Web[k];
    for (int s = sc*128 + warp; s < sc*128 + 128; s += 16) {
        const uint4* row0 = (const uint4*)(g_Whs + ((size_t)kb*SS + s)*HH);
        const uint4* row1 = (const uint4*)(g_Whs + ((size_t)kb*SS + s + 8)*HH);
        uint4 raw0[3], raw1[3];
        #pragma unroll
        for (int i = 0; i < 3; i++) { raw0[i] = row0[lane + i*32]; raw1[i] = row1[lane + i*32]; }
        __half2 acc0 = __floats2half2_rn(0.f, 0.f);
        __half2 acc1 = __floats2half2_rn(0.f, 0.f);
        #pragma unroll
        for (int i = 0; i < 3; i++) {
            int idx = lane + i*32;
            const __half2* h0 = (const __half2*)&raw0[i];
            const __half2* h1 = (const __half2*)&raw1[i];
            #pragma unroll
            for (int j = 0; j < 4; j++) {
                __half2 w = shW[idx*4 + j];
                __half2 e = shE[idx*4 + j];
                acc0 = __hfma2(mhk::tanh2f(__hadd2(h0[j], w)), e, acc0);
                acc1 = __hfma2(mhk::tanh2f(__hadd2(h1[j], w)), e, acc1);
            }
        }
        float s0 = __low2float(acc0) + __high2float(acc0);
        float s1 = __low2float(acc1) + __high2float(acc1);
        #pragma unroll
        for (int o = 16; o; o >>= 1) {
            s0 += __shfl_xor_sync(0xffffffffu, s0, o);
            s1 += __shfl_xor_sync(0xffffffffu, s1, o);
        }
        if (lane == 0) {
            g_scores[kb*SS + s] = s0 + web;
            g_scores[kb*SS + s + 8] = s1 + web;
        }
    }
}

// ---------------- fused softmax + alpha_linear + prob + argmax ----------------
__global__ __launch_bounds__(512)
void k_softalpha(const float* __restrict__ hw, const float* __restrict__ hb,
                 float* __restrict__ out_prob, int hop) {
    int b = blockIdx.x;
    int s = threadIdx.x;
    __shared__ float4 r4[512];
    float4 v;
    v.x = g_scores[(0*BB + b)*SS + s];
    v.y = g_scores[(1*BB + b)*SS + s];
    v.z = g_scores[(2*BB + b)*SS + s];
    v.w = g_scores[(3*BB + b)*SS + s];
    r4[s] = v;
    __syncthreads();
    for (int o = 256; o; o >>= 1) {
        if (s < o) {
            float4 a = r4[s], c = r4[s + o];
            a.x = fmaxf(a.x, c.x); a.y = fmaxf(a.y, c.y);
            a.z = fmaxf(a.z, c.z); a.w = fmaxf(a.w, c.w);
            r4[s] = a;
        }
        __syncthreads();
    }
    float4 m = r4[0];
    __syncthreads();
    float4 e;
    e.x = __expf(v.x - m.x); e.y = __expf(v.y - m.y);
    e.z = __expf(v.z - m.z); e.w = __expf(v.w - m.w);
    r4[s] = e;
    __syncthreads();
    for (int o = 256; o; o >>= 1) {
        if (s < o) {
            float4 a = r4[s], c = r4[s + o];
            a.x += c.x; a.y += c.y; a.z += c.z; a.w += c.w;
            r4[s] = a;
        }
        __syncthreads();
    }
    float4 Z = r4[0];
    float al = hb[0]
             + __fdividef(e.x, Z.x) * hw[0]
             + __fdividef(e.y, Z.y) * hw[1]
             + __fdividef(e.z, Z.z) * hw[2]
             + __fdividef(e.w, Z.w) * hw[3];
    __syncthreads();
    __shared__ float ssq[512];
    __shared__ float sval[512];
    __shared__ int   sidx[512];
    ssq[s] = al * al; sval[s] = al; sidx[s] = s;
    __syncthreads();
    for (int o = 256; o; o >>= 1) {
        if (s < o) {
            ssq[s] += ssq[s + o];
            float v2 = sval[s + o]; int i2 = sidx[s + o];
            if (v2 > sval[s] || (v2 == sval[s] && i2 < sidx[s])) { sval[s] = v2; sidx[s] = i2; }
        }
        __syncthreads();
    }
    if (s == 0) g_idx[b] = sidx[0];
    if (hop == 0) out_prob[b*SS + s] = al / sqrtf(ssq[0]);
}

// ---------------- GRU ----------------
__global__ void k_gru_init(const float* __restrict__ bih, const float* __restrict__ bhh) {
    int t = blockIdx.x * 256 + threadIdx.x;
    if (t < BB*H3) { int j = t % H3; g_GX[t] = bih[j]; g_GH[t] = bhh[j]; }
}

__global__ void k_grugemm(const float* __restrict__ Wih, const float* __restrict__ Whh,
                          const float* __restrict__ text) {
    int jc = blockIdx.x;
    int ks = blockIdx.y;
    int bg = blockIdx.z;
    int t = threadIdx.x;
    int j = jc*256 + t;
    int i0 = ks*256;
    __shared__ float xs[8][256];
    int i = i0 + t;
    #pragma unroll
    for (int r = 0; r < 8; r++) {
        int b = bg*8 + r;
        float v;
        if (i < 768)       v = g_qbuf[b*HH + i];
        else if (i < 1536) v = text[((size_t)b*SS + g_idx[b])*HH + (i - 768)];
        else               v = g_hbuf[b*HH + (i - 1536)];
        xs[r][t] = v;
    }
    __syncthreads();
    const float* W; int wi0; float* G;
    if (i0 < 1536) { W = Wih; wi0 = i0;        G = g_GX; }
    else           { W = Whh; wi0 = i0 - 1536; G = g_GH; }
    float acc[8];
    #pragma unroll
    for (int r = 0; r < 8; r++) acc[r] = 0.f;
    #pragma unroll 4
    for (int kk = 0; kk < 256; kk++) {
        float w = W[(size_t)(wi0 + kk)*H3 + j];
        #pragma unroll
        for (int r = 0; r < 8; r++) acc[r] = fmaf(xs[r][kk], w, acc[r]);
    }
    #pragma unroll
    for (int r = 0; r < 8; r++) atomicAdd(&G[(bg*8 + r)*H3 + j], acc[r]);
}

__global__ void k_grugate(float* __restrict__ out_h, int hop) {
    int t = blockIdx.x * 256 + threadIdx.x;
    if (t >= BB*HH) return;
    int b = t / HH, j = t % HH;
    float gxr = g_GX[b*H3 + j],        ghr = g_GH[b*H3 + j];
    float gxz = g_GX[b*H3 + HH + j],   ghz = g_GH[b*H3 + HH + j];
    float gxn = g_GX[b*H3 + 2*HH + j], ghn = g_GH[b*H3 + 2*HH + j];
    float r = 1.f / (1.f + expf(-(gxr + ghr)));
    float z = 1.f / (1.f + expf(-(gxz + ghz)));
    float n = tanhf(gxn + r * ghn);
    float hprev = g_hbuf[t];
    float hn = (1.f - z) * n + z * hprev;
    g_hbuf[t] = hn;
    g_qbuf[t] = hn;
    out_h[((size_t)b*HOPS + hop)*HH + j] = hn;
}

// ---------------- launch ----------------
extern "C" void kernel_launch(void* const* d_in, const int* in_sizes, int n_in,
                              void* d_out, int out_size) {
    const float* question = (const float*)d_in[0];
    const float* text     = (const float*)d_in[1];
    const float* pw_W     = (const float*)d_in[2];
    const float* pw_b     = (const float*)d_in[3];
    const float* Ws_W     = (const float*)d_in[4];
    const float* Ws_b     = (const float*)d_in[5];
    const float* Wt_W     = (const float*)d_in[6];
    const float* Wt_b     = (const float*)d_in[7];
    const float* We_W     = (const float*)d_in[8];
    const float* We_b     = (const float*)d_in[9];
    const float* headw_W  = (const float*)d_in[10];
    const float* headw_b  = (const float*)d_in[11];
    const float* gru_Wih  = (const float*)d_in[12];
    const float* gru_Whh  = (const float*)d_in[13];
    const float* gru_bih  = (const float*)d_in[14];
    const float* gru_bhh  = (const float*)d_in[15];

    float* out_prob = (float*)d_out;
    float* out_h    = (float*)d_out + BB*SS;

    float *p_WcT, *p_bc;
    __half *p_Whs, *p_tAh, *p_Bh;
    __nv_bfloat16 *p_pwhi, *p_pwlo, *p_WsThi, *p_WsTlo;
    cudaGetSymbolAddress((void**)&p_WcT,   g_WcT);
    cudaGetSymbolAddress((void**)&p_bc,    g_bc);
    cudaGetSymbolAddress((void**)&p_Whs,   g_Whs);
    cudaGetSymbolAddress((void**)&p_tAh,   g_tAh);
    cudaGetSymbolAddress((void**)&p_Bh,    g_Bh);
    cudaGetSymbolAddress((void**)&p_pwhi,  g_pwhi);
    cudaGetSymbolAddress((void**)&p_pwlo,  g_pwlo);
    cudaGetSymbolAddress((void**)&p_WsThi, g_WsThi);
    cudaGetSymbolAddress((void**)&p_WsTlo, g_WsTlo);

    cudaFuncSetAttribute(k_hmma3,  cudaFuncAttributeMaxDynamicSharedMemorySize, SMEM3);
    cudaFuncSetAttribute(k_fgemm2, cudaFuncAttributeMaxDynamicSharedMemorySize, F2SMEM);

    k_prologue<<<(BB*HH + 255)/256, 256>>>(question);
    k_bc<<<dim3(KK, HH/256), 256>>>(pw_b, Ws_W, Ws_b);

    // fp16 convert of text (A operand, single product)
    k_cvtH<<<(MROWS*HH + 255)/256, 256>>>(text, p_tAh, MROWS*HH);

    // bf16 splits for the small Wc GEMM
    k_split<<<(KK*HH*HH + 255)/256, 256>>>(pw_W, p_pwhi, p_pwlo, KK*HH*HH);
    k_splitT<<<dim3(HH/32, HH/32, KK), dim3(32, 8)>>>(Ws_W, p_WsThi, p_WsTlo);

    // WcT[k] = WsT[k] (.) pw[k]  ->  WcT rows = output cols (operand swap)
    k_hmma3<<<dim3(HH/128, HH/128, KK), 256, SMEM3>>>(
        p_WsThi, p_WsTlo, (size_t)HH*HH,
        p_pwhi, p_pwlo, (size_t)HH*HH,
        p_WcT, (size_t)HH*HH, nullptr, HH);

    // WcT -> fp16 (B operand)
    k_cvtH<<<(KK*HH*HH + 255)/256, 256>>>(p_WcT, p_Bh, KK*HH*HH);

    // W_hs[k] = text @ Wc[k] + bc[k]  (fp16 single-product HMMA), output fp16
    k_fgemm2<<<dim3(HH/128, MROWS/128, KK), 256, F2SMEM>>>(
        p_tAh, p_Bh, p_Whs, p_bc);

    for (int hop = 0; hop < HOPS; hop++) {
        k_init_wht<<<(KK*BB*HH + 255)/256, 256>>>(Wt_b);
        k_wht<<<dim3(KK, HH/128, HH/128), 128>>>(Wt_W);
        k_scores<<<dim3(KK*BB, SS/128), 256>>>(We_W, We_b);
        k_softalpha<<<BB, 512>>>(headw_W, headw_b, out_prob, hop);
        k_gru_init<<<(BB*H3 + 255)/256, 256>>>(gru_bih, gru_bhh);
        k_grugemm<<<dim3(H3/256, H3/256, BB/8), 256>>>(gru_Wih, gru_Whh, text);
        k_grugate<<<(BB*HH + 255)/256, 256>>>(out_h, hop);
    }
}